// round 1
// baseline (speedup 1.0000x reference)
#include <cuda_runtime.h>
#include <cstdint>

#define G_DATA  262144
#define G_TRUNC 40000
#define NEDGE   1048576
#define FEAT    128
#define EPSV    1e-8f

// Scratch in __device__ globals (no allocation allowed anywhere).
__device__ float g_xc[(size_t)G_TRUNC * FEAT];   // 20.5 MB intermediate (L2-resident)
__device__ float g_norm_down[G_TRUNC];
__device__ float g_norm_up[G_DATA];

// Zero everything: d_out (33.55M floats), g_xc, norm arrays.
__global__ void zero_kernel(float* __restrict__ out, int out_n4) {
    int idx = blockIdx.x * blockDim.x + threadIdx.x;
    int stride = gridDim.x * blockDim.x;
    float4 z = make_float4(0.f, 0.f, 0.f, 0.f);
    float4* o4  = reinterpret_cast<float4*>(out);
    float4* xc4 = reinterpret_cast<float4*>(g_xc);
    const int n_xc4 = (G_TRUNC * FEAT) / 4;
    for (int i = idx; i < out_n4; i += stride) o4[i] = z;
    for (int i = idx; i < n_xc4;  i += stride) xc4[i] = z;
    for (int i = idx; i < G_TRUNC; i += stride) g_norm_down[i] = 0.f;
    for (int i = idx; i < G_DATA;  i += stride) g_norm_up[i] = 0.f;
}

// Accumulate per-destination weight sums for both hops in one pass.
__global__ void norm_kernel(const int* __restrict__ down_dst, const float* __restrict__ down_w,
                            const int* __restrict__ up_dst,   const float* __restrict__ up_w) {
    int e = blockIdx.x * blockDim.x + threadIdx.x;
    if (e < NEDGE) {
        atomicAdd(&g_norm_down[down_dst[e]], down_w[e]);
        atomicAdd(&g_norm_up[up_dst[e]],     up_w[e]);
    }
}

// One warp per edge. Gather a 512B source row (LDG.128/lane), scale by the
// pre-normalized weight, vectorized reduction-add into the destination row.
__device__ __forceinline__ void red_add_v4(float* p, float a, float b, float c, float d) {
    asm volatile("red.global.add.v4.f32 [%0], {%1, %2, %3, %4};"
                 :: "l"(p), "f"(a), "f"(b), "f"(c), "f"(d) : "memory");
}

__global__ void __launch_bounds__(256) down_kernel(
    const float* __restrict__ x,          // points at the x[:, -1] slice
    const int*   __restrict__ src,
    const int*   __restrict__ dst,
    const float* __restrict__ w)
{
    int warp = (blockIdx.x * blockDim.x + threadIdx.x) >> 5;
    int lane = threadIdx.x & 31;
    if (warp >= NEDGE) return;
    int s = __ldg(&src[warp]);
    int d = __ldg(&dst[warp]);
    float scale = __ldg(&w[warp]) / fmaxf(g_norm_down[d], EPSV);
    const float4* row = reinterpret_cast<const float4*>(x + (size_t)s * FEAT);
    float4 v = __ldg(&row[lane]);
    float* o = &g_xc[(size_t)d * FEAT + lane * 4];
    red_add_v4(o, v.x * scale, v.y * scale, v.z * scale, v.w * scale);
}

__global__ void __launch_bounds__(256) up_kernel(
    float*       __restrict__ out,
    const int*   __restrict__ src,
    const int*   __restrict__ dst,
    const float* __restrict__ w)
{
    int warp = (blockIdx.x * blockDim.x + threadIdx.x) >> 5;
    int lane = threadIdx.x & 31;
    if (warp >= NEDGE) return;
    int s = __ldg(&src[warp]);
    int d = __ldg(&dst[warp]);
    float scale = __ldg(&w[warp]) / fmaxf(g_norm_up[d], EPSV);
    const float4* row = reinterpret_cast<const float4*>(g_xc + (size_t)s * FEAT);
    float4 v = __ldg(&row[lane]);
    float* o = &out[(size_t)d * FEAT + lane * 4];
    red_add_v4(o, v.x * scale, v.y * scale, v.z * scale, v.w * scale);
}

extern "C" void kernel_launch(void* const* d_in, const int* in_sizes, int n_in,
                              void* d_out, int out_size) {
    const float* x        = (const float*)d_in[0];   // (1,2,1,G_DATA,FEAT)
    const int*   down_src = (const int*)  d_in[1];
    const int*   down_dst = (const int*)  d_in[2];
    const float* down_w   = (const float*)d_in[3];
    const int*   up_src   = (const int*)  d_in[4];
    const int*   up_dst   = (const int*)  d_in[5];
    const float* up_w     = (const float*)d_in[6];
    float* out = (float*)d_out;

    // x[:, -1, ...] slice starts at element offset G_DATA*FEAT.
    const float* x_slice = x + (size_t)G_DATA * FEAT;

    (void)in_sizes; (void)n_in;

    // 1) Zero output + scratch.
    zero_kernel<<<2048, 256>>>(out, out_size / 4);

    // 2) Per-destination weight sums (both hops fused).
    norm_kernel<<<(NEDGE + 255) / 256, 256>>>(down_dst, down_w, up_dst, up_w);

    // 3) Down projection: 1 warp per edge, 8 warps per block.
    down_kernel<<<NEDGE / 8, 256>>>(x_slice, down_src, down_dst, down_w);

    // 4) Up projection into the output.
    up_kernel<<<NEDGE / 8, 256>>>(out, up_src, up_dst, up_w);
}

// round 2
// speedup vs baseline: 1.6098x; 1.6098x over previous
#include <cuda_runtime.h>
#include <cstdint>

#define G_DATA  262144
#define G_TRUNC 40000
#define NEDGE   1048576
#define FEAT    128
#define EPSV    1e-8f

// ---------------- scratch (__device__ globals; no allocation allowed) --------
__device__ float g_xc[(size_t)G_TRUNC * FEAT];        // 20.5 MB intermediate
__device__ int   g_cnt_down[G_TRUNC];
__device__ int   g_cnt_up[G_DATA];
__device__ int   g_off_down[G_TRUNC + 1];
__device__ int   g_off_up[G_DATA + 1];
__device__ int   g_bsum_down[256];
__device__ int   g_bsum_up[256];
__device__ int2  g_edges_down[NEDGE];                 // (src, w bits) sorted by dst
__device__ int2  g_edges_up[NEDGE];

// ---------------- CSR build --------------------------------------------------

__global__ void zero_counts_kernel() {
    int i = blockIdx.x * blockDim.x + threadIdx.x;
    int stride = gridDim.x * blockDim.x;
    for (int j = i; j < G_DATA; j += stride) g_cnt_up[j] = 0;
    for (int j = i; j < G_TRUNC; j += stride) g_cnt_down[j] = 0;
}

__global__ void hist_kernel(const int* __restrict__ ddst, const int* __restrict__ udst) {
    int i = blockIdx.x * blockDim.x + threadIdx.x;
    if (i < NEDGE) {
        atomicAdd(&g_cnt_down[ddst[i]], 1);
        atomicAdd(&g_cnt_up[udst[i]], 1);
    }
}

// Per-block (1024-elem chunk) sums.
__global__ void scan_partial(const int* __restrict__ cnt, int* __restrict__ bsum, int n) {
    __shared__ int red[256];
    int base = blockIdx.x * 1024 + threadIdx.x * 4;
    int s = 0;
#pragma unroll
    for (int j = 0; j < 4; j++) { int i = base + j; if (i < n) s += cnt[i]; }
    red[threadIdx.x] = s;
    __syncthreads();
    for (int off = 128; off > 0; off >>= 1) {
        if (threadIdx.x < off) red[threadIdx.x] += red[threadIdx.x + off];
        __syncthreads();
    }
    if (threadIdx.x == 0) bsum[blockIdx.x] = red[0];
}

// Exclusive scan of <=256 block sums (single block). Also writes off[n] = total.
__global__ void scan_bsum(int* __restrict__ bsum, int nblk, int* __restrict__ off, int n) {
    __shared__ int s[256];
    int t = threadIdx.x;
    int v = (t < nblk) ? bsum[t] : 0;
    s[t] = v;
    __syncthreads();
    for (int o = 1; o < 256; o <<= 1) {
        int add = 0;
        if (t >= o) add = s[t - o];
        __syncthreads();
        s[t] += add;
        __syncthreads();
    }
    int incl = s[t];
    if (t < nblk) bsum[t] = incl - v;              // exclusive block offset
    if (t == nblk - 1) off[n] = incl;              // grand total
}

// Final per-element exclusive scan; also zeroes cnt so it can be the scatter cursor.
__global__ void scan_final(int* __restrict__ cnt, int* __restrict__ off,
                           const int* __restrict__ bsum, int n) {
    int t = threadIdx.x;
    int lane = t & 31, wid = t >> 5;
    int base = blockIdx.x * 1024 + t * 4;
    int v0 = 0, v1 = 0, v2 = 0, v3 = 0;
    if (base + 0 < n) v0 = cnt[base + 0];
    if (base + 1 < n) v1 = cnt[base + 1];
    if (base + 2 < n) v2 = cnt[base + 2];
    if (base + 3 < n) v3 = cnt[base + 3];
    int tsum = v0 + v1 + v2 + v3;
    int x = tsum;
#pragma unroll
    for (int o = 1; o < 32; o <<= 1) {
        int y = __shfl_up_sync(0xffffffffu, x, o);
        if (lane >= o) x += y;
    }
    __shared__ int wsum[8];
    if (lane == 31) wsum[wid] = x;
    __syncthreads();
    if (t == 0) {
        int run = 0;
#pragma unroll
        for (int i = 0; i < 8; i++) { int tmp = wsum[i]; wsum[i] = run; run += tmp; }
    }
    __syncthreads();
    int excl = bsum[blockIdx.x] + wsum[wid] + (x - tsum);
    if (base + 0 < n) { off[base + 0] = excl; cnt[base + 0] = 0; } excl += v0;
    if (base + 1 < n) { off[base + 1] = excl; cnt[base + 1] = 0; } excl += v1;
    if (base + 2 < n) { off[base + 2] = excl; cnt[base + 2] = 0; } excl += v2;
    if (base + 3 < n) { off[base + 3] = excl; cnt[base + 3] = 0; }
}

__global__ void scatter_kernel(const int* __restrict__ dsrc, const int* __restrict__ ddst,
                               const float* __restrict__ dw,
                               const int* __restrict__ usrc, const int* __restrict__ udst,
                               const float* __restrict__ uw) {
    int i = blockIdx.x * blockDim.x + threadIdx.x;
    if (i < NEDGE) {
        {
            int d = ddst[i];
            int p = g_off_down[d] + atomicAdd(&g_cnt_down[d], 1);
            g_edges_down[p] = make_int2(dsrc[i], __float_as_int(dw[i]));
        }
        {
            int d = udst[i];
            int p = g_off_up[d] + atomicAdd(&g_cnt_up[d], 1);
            g_edges_up[p] = make_int2(usrc[i], __float_as_int(uw[i]));
        }
    }
}

// ---------------- gather-only projections ------------------------------------
// One warp per destination row. Accumulate sum(w*x) and sum(w) in registers,
// normalize, single 512B store. Two-edge unroll for MLP.

__device__ __forceinline__ void segment_reduce(
    const float* __restrict__ xin, const int2* __restrict__ edges,
    int beg, int end, int lane, float4& acc, float& sw)
{
    int e = beg;
    for (; e + 1 < end; e += 2) {
        int2 r0 = edges[e];
        int2 r1 = edges[e + 1];
        float w0 = __int_as_float(r0.y);
        float w1 = __int_as_float(r1.y);
        const float4* p0 = reinterpret_cast<const float4*>(xin + (size_t)r0.x * FEAT);
        const float4* p1 = reinterpret_cast<const float4*>(xin + (size_t)r1.x * FEAT);
        float4 a = __ldg(&p0[lane]);
        float4 b = __ldg(&p1[lane]);
        sw += w0 + w1;
        acc.x = fmaf(w0, a.x, fmaf(w1, b.x, acc.x));
        acc.y = fmaf(w0, a.y, fmaf(w1, b.y, acc.y));
        acc.z = fmaf(w0, a.z, fmaf(w1, b.z, acc.z));
        acc.w = fmaf(w0, a.w, fmaf(w1, b.w, acc.w));
    }
    if (e < end) {
        int2 r0 = edges[e];
        float w0 = __int_as_float(r0.y);
        const float4* p0 = reinterpret_cast<const float4*>(xin + (size_t)r0.x * FEAT);
        float4 a = __ldg(&p0[lane]);
        sw += w0;
        acc.x = fmaf(w0, a.x, acc.x);
        acc.y = fmaf(w0, a.y, acc.y);
        acc.z = fmaf(w0, a.z, acc.z);
        acc.w = fmaf(w0, a.w, acc.w);
    }
}

__global__ void __launch_bounds__(256) down_csr_kernel(const float* __restrict__ x) {
    int g = (blockIdx.x * blockDim.x + threadIdx.x) >> 5;
    int lane = threadIdx.x & 31;
    if (g >= G_TRUNC) return;
    int beg = g_off_down[g];
    int end = g_off_down[g + 1];
    float4 acc = make_float4(0.f, 0.f, 0.f, 0.f);
    float sw = 0.f;
    segment_reduce(x, g_edges_down, beg, end, lane, acc, sw);
    float inv = 1.f / fmaxf(sw, EPSV);
    float4* o = reinterpret_cast<float4*>(g_xc + (size_t)g * FEAT);
    o[lane] = make_float4(acc.x * inv, acc.y * inv, acc.z * inv, acc.w * inv);
}

__global__ void __launch_bounds__(256) up_csr_kernel(float* __restrict__ out) {
    int g = (blockIdx.x * blockDim.x + threadIdx.x) >> 5;
    int lane = threadIdx.x & 31;
    if (g >= G_DATA) return;
    int beg = g_off_up[g];
    int end = g_off_up[g + 1];
    float4 acc = make_float4(0.f, 0.f, 0.f, 0.f);
    float sw = 0.f;
    segment_reduce(g_xc, g_edges_up, beg, end, lane, acc, sw);
    float inv = 1.f / fmaxf(sw, EPSV);
    float4* o = reinterpret_cast<float4*>(out + (size_t)g * FEAT);
    o[lane] = make_float4(acc.x * inv, acc.y * inv, acc.z * inv, acc.w * inv);
}

// ---------------- launch -----------------------------------------------------

extern "C" void kernel_launch(void* const* d_in, const int* in_sizes, int n_in,
                              void* d_out, int out_size) {
    const float* x        = (const float*)d_in[0];   // (1,2,1,G_DATA,FEAT)
    const int*   down_src = (const int*)  d_in[1];
    const int*   down_dst = (const int*)  d_in[2];
    const float* down_w   = (const float*)d_in[3];
    const int*   up_src   = (const int*)  d_in[4];
    const int*   up_dst   = (const int*)  d_in[5];
    const float* up_w     = (const float*)d_in[6];
    float* out = (float*)d_out;
    (void)in_sizes; (void)n_in; (void)out_size;

    // x[:, -1, ...] slice = second half along dim 1.
    const float* x_slice = x + (size_t)G_DATA * FEAT;

    int* cnt_down; int* cnt_up; int* off_down; int* off_up;
    int* bsum_down; int* bsum_up; 
    cudaGetSymbolAddress((void**)&cnt_down, g_cnt_down);
    cudaGetSymbolAddress((void**)&cnt_up,   g_cnt_up);
    cudaGetSymbolAddress((void**)&off_down, g_off_down);
    cudaGetSymbolAddress((void**)&off_up,   g_off_up);
    cudaGetSymbolAddress((void**)&bsum_down, g_bsum_down);
    cudaGetSymbolAddress((void**)&bsum_up,   g_bsum_up);

    const int NBLK_DOWN = (G_TRUNC + 1023) / 1024;   // 40
    const int NBLK_UP   = (G_DATA + 1023) / 1024;    // 256

    // 1) zero counters (scatter restores them each replay, so this is required)
    zero_counts_kernel<<<512, 256>>>();
    // 2) histograms for both hops
    hist_kernel<<<NEDGE / 256, 256>>>(down_dst, up_dst);
    // 3) exclusive scans -> row offsets (also re-zeroes counts as cursors)
    scan_partial<<<NBLK_DOWN, 256>>>(cnt_down, bsum_down, G_TRUNC);
    scan_partial<<<NBLK_UP,   256>>>(cnt_up,   bsum_up,   G_DATA);
    scan_bsum<<<1, 256>>>(bsum_down, NBLK_DOWN, off_down, G_TRUNC);
    scan_bsum<<<1, 256>>>(bsum_up,   NBLK_UP,   off_up,   G_DATA);
    scan_final<<<NBLK_DOWN, 256>>>(cnt_down, off_down, bsum_down, G_TRUNC);
    scan_final<<<NBLK_UP,   256>>>(cnt_up,   off_up,   bsum_up,   G_DATA);
    // 4) bucket the edges by destination
    scatter_kernel<<<NEDGE / 256, 256>>>(down_src, down_dst, down_w,
                                         up_src, up_dst, up_w);
    // 5) gather-only projections: warp per destination row, store once
    down_csr_kernel<<<(G_TRUNC + 7) / 8, 256>>>(x_slice);
    up_csr_kernel<<<G_DATA / 8, 256>>>(out);
}

// round 3
// speedup vs baseline: 1.8532x; 1.1512x over previous
#include <cuda_runtime.h>
#include <cuda_fp16.h>
#include <cstdint>

#define G_DATA  262144
#define G_TRUNC 40000
#define NEDGE   1048576
#define FEAT    128
#define EPSV    1e-8f

// ---------------- scratch (__device__ globals; no allocation allowed) --------
__device__ __half g_xc[(size_t)G_TRUNC * FEAT];       // 10.2 MB fp16 intermediate
__device__ int   g_cnt_down[G_TRUNC];
__device__ int   g_cnt_up[G_DATA];
__device__ int   g_off_down[G_TRUNC + 1];
__device__ int   g_off_up[G_DATA + 1];
__device__ int   g_bsum_down[256];
__device__ int   g_bsum_up[256];
__device__ int2  g_edges_down[NEDGE];                 // (src, w bits) sorted by dst
__device__ int2  g_edges_up[NEDGE];

// ---------------- CSR build --------------------------------------------------

__global__ void zero_counts_kernel() {
    int i = blockIdx.x * blockDim.x + threadIdx.x;
    int stride = gridDim.x * blockDim.x;
    for (int j = i; j < G_DATA; j += stride) g_cnt_up[j] = 0;
    for (int j = i; j < G_TRUNC; j += stride) g_cnt_down[j] = 0;
}

__global__ void hist_kernel(const int* __restrict__ ddst, const int* __restrict__ udst) {
    int i = blockIdx.x * blockDim.x + threadIdx.x;
    if (i < NEDGE) {
        atomicAdd(&g_cnt_down[ddst[i]], 1);
        atomicAdd(&g_cnt_up[udst[i]], 1);
    }
}

// Per-block (1024-elem chunk) sums.
__global__ void scan_partial(const int* __restrict__ cnt, int* __restrict__ bsum, int n) {
    __shared__ int red[256];
    int base = blockIdx.x * 1024 + threadIdx.x * 4;
    int s = 0;
#pragma unroll
    for (int j = 0; j < 4; j++) { int i = base + j; if (i < n) s += cnt[i]; }
    red[threadIdx.x] = s;
    __syncthreads();
    for (int off = 128; off > 0; off >>= 1) {
        if (threadIdx.x < off) red[threadIdx.x] += red[threadIdx.x + off];
        __syncthreads();
    }
    if (threadIdx.x == 0) bsum[blockIdx.x] = red[0];
}

// Exclusive scan of <=256 block sums (single block). Also writes off[n] = total.
__global__ void scan_bsum(int* __restrict__ bsum, int nblk, int* __restrict__ off, int n) {
    __shared__ int s[256];
    int t = threadIdx.x;
    int v = (t < nblk) ? bsum[t] : 0;
    s[t] = v;
    __syncthreads();
    for (int o = 1; o < 256; o <<= 1) {
        int add = 0;
        if (t >= o) add = s[t - o];
        __syncthreads();
        s[t] += add;
        __syncthreads();
    }
    int incl = s[t];
    if (t < nblk) bsum[t] = incl - v;              // exclusive block offset
    if (t == nblk - 1) off[n] = incl;              // grand total
}

// Final per-element exclusive scan; also zeroes cnt so it can be the scatter cursor.
__global__ void scan_final(int* __restrict__ cnt, int* __restrict__ off,
                           const int* __restrict__ bsum, int n) {
    int t = threadIdx.x;
    int lane = t & 31, wid = t >> 5;
    int base = blockIdx.x * 1024 + t * 4;
    int v0 = 0, v1 = 0, v2 = 0, v3 = 0;
    if (base + 0 < n) v0 = cnt[base + 0];
    if (base + 1 < n) v1 = cnt[base + 1];
    if (base + 2 < n) v2 = cnt[base + 2];
    if (base + 3 < n) v3 = cnt[base + 3];
    int tsum = v0 + v1 + v2 + v3;
    int x = tsum;
#pragma unroll
    for (int o = 1; o < 32; o <<= 1) {
        int y = __shfl_up_sync(0xffffffffu, x, o);
        if (lane >= o) x += y;
    }
    __shared__ int wsum[8];
    if (lane == 31) wsum[wid] = x;
    __syncthreads();
    if (t == 0) {
        int run = 0;
#pragma unroll
        for (int i = 0; i < 8; i++) { int tmp = wsum[i]; wsum[i] = run; run += tmp; }
    }
    __syncthreads();
    int excl = bsum[blockIdx.x] + wsum[wid] + (x - tsum);
    if (base + 0 < n) { off[base + 0] = excl; cnt[base + 0] = 0; } excl += v0;
    if (base + 1 < n) { off[base + 1] = excl; cnt[base + 1] = 0; } excl += v1;
    if (base + 2 < n) { off[base + 2] = excl; cnt[base + 2] = 0; } excl += v2;
    if (base + 3 < n) { off[base + 3] = excl; cnt[base + 3] = 0; }
}

__global__ void scatter_kernel(const int* __restrict__ dsrc, const int* __restrict__ ddst,
                               const float* __restrict__ dw,
                               const int* __restrict__ usrc, const int* __restrict__ udst,
                               const float* __restrict__ uw) {
    int i = blockIdx.x * blockDim.x + threadIdx.x;
    if (i < NEDGE) {
        {
            int d = ddst[i];
            int p = g_off_down[d] + atomicAdd(&g_cnt_down[d], 1);
            g_edges_down[p] = make_int2(dsrc[i], __float_as_int(dw[i]));
        }
        {
            int d = udst[i];
            int p = g_off_up[d] + atomicAdd(&g_cnt_up[d], 1);
            g_edges_up[p] = make_int2(usrc[i], __float_as_int(uw[i]));
        }
    }
}

// ---------------- gather-only projections ------------------------------------

// Down: one warp per truncated row. fp32 gather (float4/lane), 4-edge unroll,
// fp32 accumulate, store fp16 (uint2 = 4 halves per lane).
__global__ void __launch_bounds__(256) down_csr_kernel(const float* __restrict__ x) {
    int g = (blockIdx.x * blockDim.x + threadIdx.x) >> 5;
    int lane = threadIdx.x & 31;
    if (g >= G_TRUNC) return;
    int beg = g_off_down[g];
    int end = g_off_down[g + 1];
    float4 acc = make_float4(0.f, 0.f, 0.f, 0.f);
    float sw = 0.f;
    int e = beg;
    for (; e + 3 < end; e += 4) {
        int2 r0 = g_edges_down[e];
        int2 r1 = g_edges_down[e + 1];
        int2 r2 = g_edges_down[e + 2];
        int2 r3 = g_edges_down[e + 3];
        float w0 = __int_as_float(r0.y), w1 = __int_as_float(r1.y);
        float w2 = __int_as_float(r2.y), w3 = __int_as_float(r3.y);
        float4 a = __ldg(&reinterpret_cast<const float4*>(x + (size_t)r0.x * FEAT)[lane]);
        float4 b = __ldg(&reinterpret_cast<const float4*>(x + (size_t)r1.x * FEAT)[lane]);
        float4 c = __ldg(&reinterpret_cast<const float4*>(x + (size_t)r2.x * FEAT)[lane]);
        float4 d = __ldg(&reinterpret_cast<const float4*>(x + (size_t)r3.x * FEAT)[lane]);
        sw += (w0 + w1) + (w2 + w3);
        acc.x = fmaf(w0, a.x, fmaf(w1, b.x, fmaf(w2, c.x, fmaf(w3, d.x, acc.x))));
        acc.y = fmaf(w0, a.y, fmaf(w1, b.y, fmaf(w2, c.y, fmaf(w3, d.y, acc.y))));
        acc.z = fmaf(w0, a.z, fmaf(w1, b.z, fmaf(w2, c.z, fmaf(w3, d.z, acc.z))));
        acc.w = fmaf(w0, a.w, fmaf(w1, b.w, fmaf(w2, c.w, fmaf(w3, d.w, acc.w))));
    }
    for (; e < end; e++) {
        int2 r0 = g_edges_down[e];
        float w0 = __int_as_float(r0.y);
        float4 a = __ldg(&reinterpret_cast<const float4*>(x + (size_t)r0.x * FEAT)[lane]);
        sw += w0;
        acc.x = fmaf(w0, a.x, acc.x);
        acc.y = fmaf(w0, a.y, acc.y);
        acc.z = fmaf(w0, a.z, acc.z);
        acc.w = fmaf(w0, a.w, acc.w);
    }
    float inv = 1.f / fmaxf(sw, EPSV);
    __half2 h01 = __floats2half2_rn(acc.x * inv, acc.y * inv);
    __half2 h23 = __floats2half2_rn(acc.z * inv, acc.w * inv);
    uint2 packed;
    packed.x = *reinterpret_cast<unsigned*>(&h01);
    packed.y = *reinterpret_cast<unsigned*>(&h23);
    reinterpret_cast<uint2*>(g_xc + (size_t)g * FEAT)[lane] = packed;
}

// Up: one warp per data row. fp16 gather (uint2 = 4 halves per lane, 256B
// coalesced row read), fp32 accumulate, fp32 store (float4/lane).
__global__ void __launch_bounds__(256) up_csr_kernel(float* __restrict__ out) {
    int g = (blockIdx.x * blockDim.x + threadIdx.x) >> 5;
    int lane = threadIdx.x & 31;
    if (g >= G_DATA) return;
    int beg = g_off_up[g];
    int end = g_off_up[g + 1];
    float4 acc = make_float4(0.f, 0.f, 0.f, 0.f);
    float sw = 0.f;
    const uint2* xc2 = reinterpret_cast<const uint2*>(g_xc);
    int e = beg;
    for (; e + 1 < end; e += 2) {
        int2 r0 = g_edges_up[e];
        int2 r1 = g_edges_up[e + 1];
        float w0 = __int_as_float(r0.y);
        float w1 = __int_as_float(r1.y);
        uint2 pa = __ldg(&xc2[(size_t)r0.x * (FEAT / 4) + lane]);
        uint2 pb = __ldg(&xc2[(size_t)r1.x * (FEAT / 4) + lane]);
        float2 a01 = __half22float2(*reinterpret_cast<__half2*>(&pa.x));
        float2 a23 = __half22float2(*reinterpret_cast<__half2*>(&pa.y));
        float2 b01 = __half22float2(*reinterpret_cast<__half2*>(&pb.x));
        float2 b23 = __half22float2(*reinterpret_cast<__half2*>(&pb.y));
        sw += w0 + w1;
        acc.x = fmaf(w0, a01.x, fmaf(w1, b01.x, acc.x));
        acc.y = fmaf(w0, a01.y, fmaf(w1, b01.y, acc.y));
        acc.z = fmaf(w0, a23.x, fmaf(w1, b23.x, acc.z));
        acc.w = fmaf(w0, a23.y, fmaf(w1, b23.y, acc.w));
    }
    if (e < end) {
        int2 r0 = g_edges_up[e];
        float w0 = __int_as_float(r0.y);
        uint2 pa = __ldg(&xc2[(size_t)r0.x * (FEAT / 4) + lane]);
        float2 a01 = __half22float2(*reinterpret_cast<__half2*>(&pa.x));
        float2 a23 = __half22float2(*reinterpret_cast<__half2*>(&pa.y));
        sw += w0;
        acc.x = fmaf(w0, a01.x, acc.x);
        acc.y = fmaf(w0, a01.y, acc.y);
        acc.z = fmaf(w0, a23.x, acc.z);
        acc.w = fmaf(w0, a23.y, acc.w);
    }
    float inv = 1.f / fmaxf(sw, EPSV);
    reinterpret_cast<float4*>(out + (size_t)g * FEAT)[lane] =
        make_float4(acc.x * inv, acc.y * inv, acc.z * inv, acc.w * inv);
}

// ---------------- launch -----------------------------------------------------

extern "C" void kernel_launch(void* const* d_in, const int* in_sizes, int n_in,
                              void* d_out, int out_size) {
    const float* x        = (const float*)d_in[0];   // (1,2,1,G_DATA,FEAT)
    const int*   down_src = (const int*)  d_in[1];
    const int*   down_dst = (const int*)  d_in[2];
    const float* down_w   = (const float*)d_in[3];
    const int*   up_src   = (const int*)  d_in[4];
    const int*   up_dst   = (const int*)  d_in[5];
    const float* up_w     = (const float*)d_in[6];
    float* out = (float*)d_out;
    (void)in_sizes; (void)n_in; (void)out_size;

    // x[:, -1, ...] slice = second half along dim 1.
    const float* x_slice = x + (size_t)G_DATA * FEAT;

    int* cnt_down; int* cnt_up; int* off_down; int* off_up;
    int* bsum_down; int* bsum_up;
    cudaGetSymbolAddress((void**)&cnt_down, g_cnt_down);
    cudaGetSymbolAddress((void**)&cnt_up,   g_cnt_up);
    cudaGetSymbolAddress((void**)&off_down, g_off_down);
    cudaGetSymbolAddress((void**)&off_up,   g_off_up);
    cudaGetSymbolAddress((void**)&bsum_down, g_bsum_down);
    cudaGetSymbolAddress((void**)&bsum_up,   g_bsum_up);

    const int NBLK_DOWN = (G_TRUNC + 1023) / 1024;   // 40
    const int NBLK_UP   = (G_DATA + 1023) / 1024;    // 256

    // 1) zero counters (scatter restores them each replay, so this is required)
    zero_counts_kernel<<<512, 256>>>();
    // 2) histograms for both hops
    hist_kernel<<<NEDGE / 256, 256>>>(down_dst, up_dst);
    // 3) exclusive scans -> row offsets (also re-zeroes counts as cursors)
    scan_partial<<<NBLK_DOWN, 256>>>(cnt_down, bsum_down, G_TRUNC);
    scan_partial<<<NBLK_UP,   256>>>(cnt_up,   bsum_up,   G_DATA);
    scan_bsum<<<1, 256>>>(bsum_down, NBLK_DOWN, off_down, G_TRUNC);
    scan_bsum<<<1, 256>>>(bsum_up,   NBLK_UP,   off_up,   G_DATA);
    scan_final<<<NBLK_DOWN, 256>>>(cnt_down, off_down, bsum_down, G_TRUNC);
    scan_final<<<NBLK_UP,   256>>>(cnt_up,   off_up,   bsum_up,   G_DATA);
    // 4) bucket the edges by destination
    scatter_kernel<<<NEDGE / 256, 256>>>(down_src, down_dst, down_w,
                                         up_src, up_dst, up_w);
    // 5) gather-only projections
    down_csr_kernel<<<(G_TRUNC + 7) / 8, 256>>>(x_slice);
    up_csr_kernel<<<G_DATA / 8, 256>>>(out);
}

// round 4
// speedup vs baseline: 1.9279x; 1.0403x over previous
#include <cuda_runtime.h>
#include <cuda_fp16.h>
#include <cstdint>

#define G_DATA  262144
#define G_TRUNC 40000
#define NEDGE   1048576
#define FEAT    128
#define EPSV    1e-8f

#define NBLK_DOWN 40     // ceil(G_TRUNC/1024)
#define NBLK_UP   256    // G_DATA/1024

// ---------------- scratch (__device__ globals; no allocation allowed) --------
__device__ __half g_xh[(size_t)G_DATA * FEAT];        // 67 MB fp16 copy of x slice
__device__ __half g_xc[(size_t)G_TRUNC * FEAT];       // 10.2 MB fp16 intermediate
__device__ int   g_cnt_down[G_TRUNC];
__device__ int   g_cnt_up[G_DATA];
__device__ int   g_off_down[G_TRUNC + 1];
__device__ int   g_off_up[G_DATA + 1];
__device__ int   g_bsum_down[NBLK_DOWN];
__device__ int   g_bsum_up[NBLK_UP];
__device__ int2  g_edges_down[NEDGE];                 // (src, w bits) sorted by dst
__device__ int2  g_edges_up[NEDGE];

// ---------------- convert x to fp16 + zero counters (fused) ------------------
__global__ void convert_zero_kernel(const float* __restrict__ x) {
    int idx = blockIdx.x * blockDim.x + threadIdx.x;
    int stride = gridDim.x * blockDim.x;
    const float4* x4 = reinterpret_cast<const float4*>(x);
    uint2* xh2 = reinterpret_cast<uint2*>(g_xh);
    const int n4 = (G_DATA * FEAT) / 4;               // 8.39M
    for (int i = idx; i < n4; i += stride) {
        float4 v = __ldg(&x4[i]);
        __half2 h01 = __floats2half2_rn(v.x, v.y);
        __half2 h23 = __floats2half2_rn(v.z, v.w);
        xh2[i] = make_uint2(*reinterpret_cast<unsigned*>(&h01),
                            *reinterpret_cast<unsigned*>(&h23));
    }
    for (int j = idx; j < G_DATA; j += stride) g_cnt_up[j] = 0;
    for (int j = idx; j < G_TRUNC; j += stride) g_cnt_down[j] = 0;
}

// ---------------- CSR build --------------------------------------------------
__global__ void hist_kernel(const int* __restrict__ ddst, const int* __restrict__ udst) {
    int i = blockIdx.x * blockDim.x + threadIdx.x;
    if (i < NEDGE) {
        atomicAdd(&g_cnt_down[ddst[i]], 1);
        atomicAdd(&g_cnt_up[udst[i]], 1);
    }
}

// Per-1024-chunk sums for both arrays in one launch (blocks [0,40)=down).
__global__ void scan_partial_both() {
    __shared__ int red[256];
    int blk = blockIdx.x;
    const int* cnt; int* bsum; int n; int b;
    if (blk < NBLK_DOWN) { cnt = g_cnt_down; bsum = g_bsum_down; n = G_TRUNC; b = blk; }
    else                 { cnt = g_cnt_up;   bsum = g_bsum_up;   n = G_DATA;  b = blk - NBLK_DOWN; }
    int base = b * 1024 + threadIdx.x * 4;
    int s = 0;
#pragma unroll
    for (int j = 0; j < 4; j++) { int i = base + j; if (i < n) s += cnt[i]; }
    red[threadIdx.x] = s;
    __syncthreads();
    for (int off = 128; off > 0; off >>= 1) {
        if (threadIdx.x < off) red[threadIdx.x] += red[threadIdx.x + off];
        __syncthreads();
    }
    if (threadIdx.x == 0) bsum[b] = red[0];
}

// Exclusive scan of block sums; block 0 = down (40), block 1 = up (256).
__global__ void scan_bsum_both() {
    __shared__ int s[256];
    int* bsum; int nblk; int* off; int n;
    if (blockIdx.x == 0) { bsum = g_bsum_down; nblk = NBLK_DOWN; off = g_off_down; n = G_TRUNC; }
    else                 { bsum = g_bsum_up;   nblk = NBLK_UP;   off = g_off_up;   n = G_DATA;  }
    int t = threadIdx.x;
    int v = (t < nblk) ? bsum[t] : 0;
    s[t] = v;
    __syncthreads();
    for (int o = 1; o < 256; o <<= 1) {
        int add = 0;
        if (t >= o) add = s[t - o];
        __syncthreads();
        s[t] += add;
        __syncthreads();
    }
    int incl = s[t];
    if (t < nblk) bsum[t] = incl - v;              // exclusive block offset
    if (t == nblk - 1) off[n] = incl;              // grand total
}

// Final per-element exclusive scan; zeroes cnt to reuse as scatter cursor.
__global__ void scan_final_both() {
    int blk = blockIdx.x;
    int* cnt; int* off; const int* bsum; int n; int b;
    if (blk < NBLK_DOWN) { cnt = g_cnt_down; off = g_off_down; bsum = g_bsum_down; n = G_TRUNC; b = blk; }
    else                 { cnt = g_cnt_up;   off = g_off_up;   bsum = g_bsum_up;   n = G_DATA;  b = blk - NBLK_DOWN; }
    int t = threadIdx.x;
    int lane = t & 31, wid = t >> 5;
    int base = b * 1024 + t * 4;
    int v0 = 0, v1 = 0, v2 = 0, v3 = 0;
    if (base + 0 < n) v0 = cnt[base + 0];
    if (base + 1 < n) v1 = cnt[base + 1];
    if (base + 2 < n) v2 = cnt[base + 2];
    if (base + 3 < n) v3 = cnt[base + 3];
    int tsum = v0 + v1 + v2 + v3;
    int x = tsum;
#pragma unroll
    for (int o = 1; o < 32; o <<= 1) {
        int y = __shfl_up_sync(0xffffffffu, x, o);
        if (lane >= o) x += y;
    }
    __shared__ int wsum[8];
    if (lane == 31) wsum[wid] = x;
    __syncthreads();
    if (t == 0) {
        int run = 0;
#pragma unroll
        for (int i = 0; i < 8; i++) { int tmp = wsum[i]; wsum[i] = run; run += tmp; }
    }
    __syncthreads();
    int excl = bsum[b] + wsum[wid] + (x - tsum);
    if (base + 0 < n) { off[base + 0] = excl; cnt[base + 0] = 0; } excl += v0;
    if (base + 1 < n) { off[base + 1] = excl; cnt[base + 1] = 0; } excl += v1;
    if (base + 2 < n) { off[base + 2] = excl; cnt[base + 2] = 0; } excl += v2;
    if (base + 3 < n) { off[base + 3] = excl; cnt[base + 3] = 0; }
}

__global__ void scatter_kernel(const int* __restrict__ dsrc, const int* __restrict__ ddst,
                               const float* __restrict__ dw,
                               const int* __restrict__ usrc, const int* __restrict__ udst,
                               const float* __restrict__ uw) {
    int i = blockIdx.x * blockDim.x + threadIdx.x;
    if (i < NEDGE) {
        {
            int d = ddst[i];
            int p = g_off_down[d] + atomicAdd(&g_cnt_down[d], 1);
            g_edges_down[p] = make_int2(dsrc[i], __float_as_int(dw[i]));
        }
        {
            int d = udst[i];
            int p = g_off_up[d] + atomicAdd(&g_cnt_up[d], 1);
            g_edges_up[p] = make_int2(usrc[i], __float_as_int(uw[i]));
        }
    }
}

// ---------------- gather-only projections ------------------------------------

__device__ __forceinline__ float4 h4_to_f4(uint2 p) {
    float2 a = __half22float2(*reinterpret_cast<__half2*>(&p.x));
    float2 b = __half22float2(*reinterpret_cast<__half2*>(&p.y));
    return make_float4(a.x, a.y, b.x, b.y);
}

// Down: one warp per truncated row. fp16 gather (uint2/lane), 4-edge unroll,
// fp32 accumulate, fp16 store.
__global__ void __launch_bounds__(256) down_csr_kernel() {
    int g = (blockIdx.x * blockDim.x + threadIdx.x) >> 5;
    int lane = threadIdx.x & 31;
    if (g >= G_TRUNC) return;
    int beg = g_off_down[g];
    int end = g_off_down[g + 1];
    const uint2* xh = reinterpret_cast<const uint2*>(g_xh);
    float4 acc = make_float4(0.f, 0.f, 0.f, 0.f);
    float sw = 0.f;
    int e = beg;
    for (; e + 3 < end; e += 4) {
        int2 r0 = g_edges_down[e];
        int2 r1 = g_edges_down[e + 1];
        int2 r2 = g_edges_down[e + 2];
        int2 r3 = g_edges_down[e + 3];
        float w0 = __int_as_float(r0.y), w1 = __int_as_float(r1.y);
        float w2 = __int_as_float(r2.y), w3 = __int_as_float(r3.y);
        float4 a = h4_to_f4(__ldg(&xh[(size_t)r0.x * (FEAT / 4) + lane]));
        float4 b = h4_to_f4(__ldg(&xh[(size_t)r1.x * (FEAT / 4) + lane]));
        float4 c = h4_to_f4(__ldg(&xh[(size_t)r2.x * (FEAT / 4) + lane]));
        float4 d = h4_to_f4(__ldg(&xh[(size_t)r3.x * (FEAT / 4) + lane]));
        sw += (w0 + w1) + (w2 + w3);
        acc.x = fmaf(w0, a.x, fmaf(w1, b.x, fmaf(w2, c.x, fmaf(w3, d.x, acc.x))));
        acc.y = fmaf(w0, a.y, fmaf(w1, b.y, fmaf(w2, c.y, fmaf(w3, d.y, acc.y))));
        acc.z = fmaf(w0, a.z, fmaf(w1, b.z, fmaf(w2, c.z, fmaf(w3, d.z, acc.z))));
        acc.w = fmaf(w0, a.w, fmaf(w1, b.w, fmaf(w2, c.w, fmaf(w3, d.w, acc.w))));
    }
    for (; e < end; e++) {
        int2 r0 = g_edges_down[e];
        float w0 = __int_as_float(r0.y);
        float4 a = h4_to_f4(__ldg(&xh[(size_t)r0.x * (FEAT / 4) + lane]));
        sw += w0;
        acc.x = fmaf(w0, a.x, acc.x);
        acc.y = fmaf(w0, a.y, acc.y);
        acc.z = fmaf(w0, a.z, acc.z);
        acc.w = fmaf(w0, a.w, acc.w);
    }
    float inv = 1.f / fmaxf(sw, EPSV);
    __half2 h01 = __floats2half2_rn(acc.x * inv, acc.y * inv);
    __half2 h23 = __floats2half2_rn(acc.z * inv, acc.w * inv);
    reinterpret_cast<uint2*>(g_xc + (size_t)g * FEAT)[lane] =
        make_uint2(*reinterpret_cast<unsigned*>(&h01),
                   *reinterpret_cast<unsigned*>(&h23));
}

// Up: one warp per data row. fp16 gather of xc, fp32 accumulate, fp32 store.
__global__ void __launch_bounds__(256) up_csr_kernel(float* __restrict__ out) {
    int g = (blockIdx.x * blockDim.x + threadIdx.x) >> 5;
    int lane = threadIdx.x & 31;
    if (g >= G_DATA) return;
    int beg = g_off_up[g];
    int end = g_off_up[g + 1];
    const uint2* xc2 = reinterpret_cast<const uint2*>(g_xc);
    float4 acc = make_float4(0.f, 0.f, 0.f, 0.f);
    float sw = 0.f;
    int e = beg;
    for (; e + 1 < end; e += 2) {
        int2 r0 = g_edges_up[e];
        int2 r1 = g_edges_up[e + 1];
        float w0 = __int_as_float(r0.y);
        float w1 = __int_as_float(r1.y);
        float4 a = h4_to_f4(__ldg(&xc2[(size_t)r0.x * (FEAT / 4) + lane]));
        float4 b = h4_to_f4(__ldg(&xc2[(size_t)r1.x * (FEAT / 4) + lane]));
        sw += w0 + w1;
        acc.x = fmaf(w0, a.x, fmaf(w1, b.x, acc.x));
        acc.y = fmaf(w0, a.y, fmaf(w1, b.y, acc.y));
        acc.z = fmaf(w0, a.z, fmaf(w1, b.z, acc.z));
        acc.w = fmaf(w0, a.w, fmaf(w1, b.w, acc.w));
    }
    if (e < end) {
        int2 r0 = g_edges_up[e];
        float w0 = __int_as_float(r0.y);
        float4 a = h4_to_f4(__ldg(&xc2[(size_t)r0.x * (FEAT / 4) + lane]));
        sw += w0;
        acc.x = fmaf(w0, a.x, acc.x);
        acc.y = fmaf(w0, a.y, acc.y);
        acc.z = fmaf(w0, a.z, acc.z);
        acc.w = fmaf(w0, a.w, acc.w);
    }
    float inv = 1.f / fmaxf(sw, EPSV);
    reinterpret_cast<float4*>(out + (size_t)g * FEAT)[lane] =
        make_float4(acc.x * inv, acc.y * inv, acc.z * inv, acc.w * inv);
}

// ---------------- launch -----------------------------------------------------

extern "C" void kernel_launch(void* const* d_in, const int* in_sizes, int n_in,
                              void* d_out, int out_size) {
    const float* x        = (const float*)d_in[0];   // (1,2,1,G_DATA,FEAT)
    const int*   down_src = (const int*)  d_in[1];
    const int*   down_dst = (const int*)  d_in[2];
    const float* down_w   = (const float*)d_in[3];
    const int*   up_src   = (const int*)  d_in[4];
    const int*   up_dst   = (const int*)  d_in[5];
    const float* up_w     = (const float*)d_in[6];
    float* out = (float*)d_out;
    (void)in_sizes; (void)n_in; (void)out_size;

    // x[:, -1, ...] slice = second half along dim 1.
    const float* x_slice = x + (size_t)G_DATA * FEAT;

    // 1) convert x to fp16 + zero counters (fused streaming pass)
    convert_zero_kernel<<<4096, 256>>>(x_slice);
    // 2) histograms for both hops
    hist_kernel<<<NEDGE / 256, 256>>>(down_dst, up_dst);
    // 3) exclusive scans -> row offsets (fused down+up per stage)
    scan_partial_both<<<NBLK_DOWN + NBLK_UP, 256>>>();
    scan_bsum_both<<<2, 256>>>();
    scan_final_both<<<NBLK_DOWN + NBLK_UP, 256>>>();
    // 4) bucket the edges by destination
    scatter_kernel<<<NEDGE / 256, 256>>>(down_src, down_dst, down_w,
                                         up_src, up_dst, up_w);
    // 5) gather-only projections
    down_csr_kernel<<<(G_TRUNC + 7) / 8, 256>>>();
    up_csr_kernel<<<G_DATA / 8, 256>>>(out);
}

// round 6
// speedup vs baseline: 1.9998x; 1.0373x over previous
#include <cuda_runtime.h>
#include <cuda_fp16.h>
#include <cstdint>

#define G_DATA  262144
#define G_TRUNC 40000
#define NEDGE   1048576
#define FEAT    128
#define EPSV    1e-8f

#define NBLK_DOWN 40     // ceil(G_TRUNC/1024)
#define NBLK_UP   256    // G_DATA/1024

// ---------------- scratch (__device__ globals; no allocation allowed) --------
// INVARIANT: g_cnt_* are zero at entry to kernel_launch. They start zero
// (static init) and the countdown scatter returns them to zero every call.
__device__ __half g_xh[(size_t)G_DATA * FEAT];        // 67 MB fp16 copy of x slice
__device__ __half g_xc[(size_t)G_TRUNC * FEAT];       // 10.2 MB fp16 intermediate
__device__ int   g_cnt_down[G_TRUNC];
__device__ int   g_cnt_up[G_DATA];
__device__ int   g_off_down[G_TRUNC + 1];
__device__ int   g_off_up[G_DATA + 1];
__device__ int   g_bsum_down[NBLK_DOWN];
__device__ int   g_bsum_up[NBLK_UP];
__device__ int2  g_edges_down[NEDGE];                 // (src, w bits) bucketed by dst
__device__ int2  g_edges_up[NEDGE];

// ---------------- CSR build --------------------------------------------------

__global__ void hist_kernel(const int* __restrict__ ddst, const int* __restrict__ udst) {
    int i = blockIdx.x * blockDim.x + threadIdx.x;
    if (i < NEDGE) {
        atomicAdd(&g_cnt_down[ddst[i]], 1);
        atomicAdd(&g_cnt_up[udst[i]], 1);
    }
}

// Per-1024-chunk sums for both arrays in one launch (blocks [0,40)=down).
__global__ void scan_partial_both() {
    __shared__ int red[256];
    int blk = blockIdx.x;
    const int* cnt; int* bsum; int n; int b;
    if (blk < NBLK_DOWN) { cnt = g_cnt_down; bsum = g_bsum_down; n = G_TRUNC; b = blk; }
    else                 { cnt = g_cnt_up;   bsum = g_bsum_up;   n = G_DATA;  b = blk - NBLK_DOWN; }
    int base = b * 1024 + threadIdx.x * 4;
    int s = 0;
#pragma unroll
    for (int j = 0; j < 4; j++) { int i = base + j; if (i < n) s += cnt[i]; }
    red[threadIdx.x] = s;
    __syncthreads();
    for (int off = 128; off > 0; off >>= 1) {
        if (threadIdx.x < off) red[threadIdx.x] += red[threadIdx.x + off];
        __syncthreads();
    }
    if (threadIdx.x == 0) bsum[b] = red[0];
}

// Per-element exclusive scan. Each block redundantly scans the (<=256) block
// sums itself — removes the separate scan_bsum launch. cnt is left intact
// (the scatter's countdown cursor consumes it back to zero).
__global__ void scan_final_both() {
    int blk = blockIdx.x;
    const int* cnt; int* off; const int* bsum; int n, nblk, b;
    if (blk < NBLK_DOWN) { cnt = g_cnt_down; off = g_off_down; bsum = g_bsum_down;
                           n = G_TRUNC; nblk = NBLK_DOWN; b = blk; }
    else                 { cnt = g_cnt_up;   off = g_off_up;   bsum = g_bsum_up;
                           n = G_DATA;  nblk = NBLK_UP;   b = blk - NBLK_DOWN; }
    int t = threadIdx.x;
    int lane = t & 31, wid = t >> 5;

    // In-block inclusive scan of the block sums.
    __shared__ int s[256];
    int bv = (t < nblk) ? bsum[t] : 0;
    s[t] = bv;
    __syncthreads();
    for (int o = 1; o < 256; o <<= 1) {
        int add = (t >= o) ? s[t - o] : 0;
        __syncthreads();
        s[t] += add;
        __syncthreads();
    }
    int block_off = (b > 0) ? s[b - 1] : 0;
    if (b == 0 && t == 0) off[n] = s[nblk - 1];   // grand total

    int base = b * 1024 + t * 4;
    int v0 = 0, v1 = 0, v2 = 0, v3 = 0;
    if (base + 0 < n) v0 = cnt[base + 0];
    if (base + 1 < n) v1 = cnt[base + 1];
    if (base + 2 < n) v2 = cnt[base + 2];
    if (base + 3 < n) v3 = cnt[base + 3];
    int tsum = v0 + v1 + v2 + v3;
    int x = tsum;
#pragma unroll
    for (int o = 1; o < 32; o <<= 1) {
        int y = __shfl_up_sync(0xffffffffu, x, o);
        if (lane >= o) x += y;
    }
    __shared__ int wsum[8];
    if (lane == 31) wsum[wid] = x;
    __syncthreads();
    if (t == 0) {
        int run = 0;
#pragma unroll
        for (int i = 0; i < 8; i++) { int tmp = wsum[i]; wsum[i] = run; run += tmp; }
    }
    __syncthreads();
    int excl = block_off + wsum[wid] + (x - tsum);
    if (base + 0 < n) off[base + 0] = excl; excl += v0;
    if (base + 1 < n) off[base + 1] = excl; excl += v1;
    if (base + 2 < n) off[base + 2] = excl; excl += v2;
    if (base + 3 < n) off[base + 3] = excl;
}

// Countdown cursor: cnt[d] holds the bucket count; atomicAdd(-1) hands out
// slots c-1..0 and leaves cnt at exactly 0 for the next call.
__global__ void scatter_kernel(const int* __restrict__ dsrc, const int* __restrict__ ddst,
                               const float* __restrict__ dw,
                               const int* __restrict__ usrc, const int* __restrict__ udst,
                               const float* __restrict__ uw) {
    int i = blockIdx.x * blockDim.x + threadIdx.x;
    if (i < NEDGE) {
        {
            int d = ddst[i];
            int idx = atomicAdd(&g_cnt_down[d], -1);
            g_edges_down[g_off_down[d] + idx - 1] = make_int2(dsrc[i], __float_as_int(dw[i]));
        }
        {
            int d = udst[i];
            int idx = atomicAdd(&g_cnt_up[d], -1);
            g_edges_up[g_off_up[d] + idx - 1] = make_int2(usrc[i], __float_as_int(uw[i]));
        }
    }
}

// ---------------- convert x to fp16 (runs right before down: keeps xh L2-hot) -
__global__ void convert_kernel(const float* __restrict__ x) {
    int idx = blockIdx.x * blockDim.x + threadIdx.x;
    int stride = gridDim.x * blockDim.x;
    const float4* x4 = reinterpret_cast<const float4*>(x);
    uint2* xh2 = reinterpret_cast<uint2*>(g_xh);
    const int n4 = (G_DATA * FEAT) / 4;               // 8.39M
    for (int i = idx; i < n4; i += stride) {
        float4 v = __ldcs(&x4[i]);                    // streaming read, no L2 pollution
        __half2 h01 = __floats2half2_rn(v.x, v.y);
        __half2 h23 = __floats2half2_rn(v.z, v.w);
        xh2[i] = make_uint2(*reinterpret_cast<unsigned*>(&h01),
                            *reinterpret_cast<unsigned*>(&h23));
    }
}

// ---------------- gather-only projections ------------------------------------

__device__ __forceinline__ float4 h4_to_f4(uint2 p) {
    float2 a = __half22float2(*reinterpret_cast<__half2*>(&p.x));
    float2 b = __half22float2(*reinterpret_cast<__half2*>(&p.y));
    return make_float4(a.x, a.y, b.x, b.y);
}

// Down: one warp per truncated row. fp16 gather, 4-edge unroll, fp32
// accumulate, fp16 store.
__global__ void __launch_bounds__(256) down_csr_kernel() {
    int g = (blockIdx.x * blockDim.x + threadIdx.x) >> 5;
    int lane = threadIdx.x & 31;
    if (g >= G_TRUNC) return;
    int beg = g_off_down[g];
    int end = g_off_down[g + 1];
    const uint2* xh = reinterpret_cast<const uint2*>(g_xh);
    float4 acc = make_float4(0.f, 0.f, 0.f, 0.f);
    float sw = 0.f;
    int e = beg;
    for (; e + 3 < end; e += 4) {
        int2 r0 = g_edges_down[e];
        int2 r1 = g_edges_down[e + 1];
        int2 r2 = g_edges_down[e + 2];
        int2 r3 = g_edges_down[e + 3];
        float w0 = __int_as_float(r0.y), w1 = __int_as_float(r1.y);
        float w2 = __int_as_float(r2.y), w3 = __int_as_float(r3.y);
        float4 a = h4_to_f4(__ldg(&xh[(size_t)r0.x * (FEAT / 4) + lane]));
        float4 b = h4_to_f4(__ldg(&xh[(size_t)r1.x * (FEAT / 4) + lane]));
        float4 c = h4_to_f4(__ldg(&xh[(size_t)r2.x * (FEAT / 4) + lane]));
        float4 d = h4_to_f4(__ldg(&xh[(size_t)r3.x * (FEAT / 4) + lane]));
        sw += (w0 + w1) + (w2 + w3);
        acc.x = fmaf(w0, a.x, fmaf(w1, b.x, fmaf(w2, c.x, fmaf(w3, d.x, acc.x))));
        acc.y = fmaf(w0, a.y, fmaf(w1, b.y, fmaf(w2, c.y, fmaf(w3, d.y, acc.y))));
        acc.z = fmaf(w0, a.z, fmaf(w1, b.z, fmaf(w2, c.z, fmaf(w3, d.z, acc.z))));
        acc.w = fmaf(w0, a.w, fmaf(w1, b.w, fmaf(w2, c.w, fmaf(w3, d.w, acc.w))));
    }
    for (; e < end; e++) {
        int2 r0 = g_edges_down[e];
        float w0 = __int_as_float(r0.y);
        float4 a = h4_to_f4(__ldg(&xh[(size_t)r0.x * (FEAT / 4) + lane]));
        sw += w0;
        acc.x = fmaf(w0, a.x, acc.x);
        acc.y = fmaf(w0, a.y, acc.y);
        acc.z = fmaf(w0, a.z, acc.z);
        acc.w = fmaf(w0, a.w, acc.w);
    }
    float inv = 1.f / fmaxf(sw, EPSV);
    __half2 h01 = __floats2half2_rn(acc.x * inv, acc.y * inv);
    __half2 h23 = __floats2half2_rn(acc.z * inv, acc.w * inv);
    reinterpret_cast<uint2*>(g_xc + (size_t)g * FEAT)[lane] =
        make_uint2(*reinterpret_cast<unsigned*>(&h01),
                   *reinterpret_cast<unsigned*>(&h23));
}

// Up: one warp per data row. fp16 gather of xc, 4-edge unroll, fp32
// accumulate, streaming fp32 store.
__global__ void __launch_bounds__(256) up_csr_kernel(float* __restrict__ out) {
    int g = (blockIdx.x * blockDim.x + threadIdx.x) >> 5;
    int lane = threadIdx.x & 31;
    if (g >= G_DATA) return;
    int beg = g_off_up[g];
    int end = g_off_up[g + 1];
    const uint2* xc2 = reinterpret_cast<const uint2*>(g_xc);
    float4 acc = make_float4(0.f, 0.f, 0.f, 0.f);
    float sw = 0.f;
    int e = beg;
    for (; e + 3 < end; e += 4) {
        int2 r0 = g_edges_up[e];
        int2 r1 = g_edges_up[e + 1];
        int2 r2 = g_edges_up[e + 2];
        int2 r3 = g_edges_up[e + 3];
        float w0 = __int_as_float(r0.y), w1 = __int_as_float(r1.y);
        float w2 = __int_as_float(r2.y), w3 = __int_as_float(r3.y);
        float4 a = h4_to_f4(__ldg(&xc2[(size_t)r0.x * (FEAT / 4) + lane]));
        float4 b = h4_to_f4(__ldg(&xc2[(size_t)r1.x * (FEAT / 4) + lane]));
        float4 c = h4_to_f4(__ldg(&xc2[(size_t)r2.x * (FEAT / 4) + lane]));
        float4 d = h4_to_f4(__ldg(&xc2[(size_t)r3.x * (FEAT / 4) + lane]));
        sw += (w0 + w1) + (w2 + w3);
        acc.x = fmaf(w0, a.x, fmaf(w1, b.x, fmaf(w2, c.x, fmaf(w3, d.x, acc.x))));
        acc.y = fmaf(w0, a.y, fmaf(w1, b.y, fmaf(w2, c.y, fmaf(w3, d.y, acc.y))));
        acc.z = fmaf(w0, a.z, fmaf(w1, b.z, fmaf(w2, c.z, fmaf(w3, d.z, acc.z))));
        acc.w = fmaf(w0, a.w, fmaf(w1, b.w, fmaf(w2, c.w, fmaf(w3, d.w, acc.w))));
    }
    for (; e < end; e++) {
        int2 r0 = g_edges_up[e];
        float w0 = __int_as_float(r0.y);
        float4 a = h4_to_f4(__ldg(&xc2[(size_t)r0.x * (FEAT / 4) + lane]));
        sw += w0;
        acc.x = fmaf(w0, a.x, acc.x);
        acc.y = fmaf(w0, a.y, acc.y);
        acc.z = fmaf(w0, a.z, acc.z);
        acc.w = fmaf(w0, a.w, acc.w);
    }
    float inv = 1.f / fmaxf(sw, EPSV);
    __stcs(reinterpret_cast<float4*>(out + (size_t)g * FEAT) + lane,
           make_float4(acc.x * inv, acc.y * inv, acc.z * inv, acc.w * inv));
}

// ---------------- launch -----------------------------------------------------

extern "C" void kernel_launch(void* const* d_in, const int* in_sizes, int n_in,
                              void* d_out, int out_size) {
    const float* x        = (const float*)d_in[0];   // (1,2,1,G_DATA,FEAT)
    const int*   down_src = (const int*)  d_in[1];
    const int*   down_dst = (const int*)  d_in[2];
    const float* down_w   = (const float*)d_in[3];
    const int*   up_src   = (const int*)  d_in[4];
    const int*   up_dst   = (const int*)  d_in[5];
    const float* up_w     = (const float*)d_in[6];
    float* out = (float*)d_out;
    (void)in_sizes; (void)n_in; (void)out_size;

    // x[:, -1, ...] slice = second half along dim 1.
    const float* x_slice = x + (size_t)G_DATA * FEAT;

    // CSR build (counters are zero at entry — countdown invariant)
    hist_kernel<<<NEDGE / 256, 256>>>(down_dst, up_dst);
    scan_partial_both<<<NBLK_DOWN + NBLK_UP, 256>>>();
    scan_final_both<<<NBLK_DOWN + NBLK_UP, 256>>>();
    scatter_kernel<<<NEDGE / 256, 256>>>(down_src, down_dst, down_w,
                                         up_src, up_dst, up_w);
    // Convert x right before down so g_xh is L2-hot for the gather.
    convert_kernel<<<4096, 256>>>(x_slice);
    // Gather-only projections
    down_csr_kernel<<<(G_TRUNC + 7) / 8, 256>>>();
    up_csr_kernel<<<G_DATA / 8, 256>>>(out);
}

// round 7
// speedup vs baseline: 2.1171x; 1.0587x over previous
#include <cuda_runtime.h>
#include <cuda_fp16.h>
#include <cstdint>

#define G_DATA  262144
#define G_TRUNC 40000
#define NEDGE   1048576
#define FEAT    128
#define EPSV    1e-8f

#define NBLK_DOWN 40     // ceil(G_TRUNC/1024)
#define NBLK_UP   256    // G_DATA/1024

// ---------------- scratch (__device__ globals; no allocation allowed) --------
// INVARIANT: g_cnt_* are zero at entry to kernel_launch. They start zero
// (static init) and the countdown scatter returns them to zero every call.
__device__ __half g_xh[(size_t)G_DATA * FEAT];        // 67 MB fp16 copy of x slice
__device__ __half g_xc[(size_t)G_TRUNC * FEAT];       // 10.2 MB fp16 intermediate
__device__ int   g_cnt_down[G_TRUNC];
__device__ int   g_cnt_up[G_DATA];
__device__ int   g_off_down[G_TRUNC + 1];
__device__ int   g_off_up[G_DATA + 1];
__device__ int   g_bsum_down[NBLK_DOWN];
__device__ int   g_bsum_up[NBLK_UP];
__device__ int2  g_edges_down[NEDGE];                 // (src, w bits) bucketed by dst
__device__ int2  g_edges_up[NEDGE];

// ---------------- CSR build --------------------------------------------------

__global__ void hist_kernel(const int* __restrict__ ddst, const int* __restrict__ udst) {
    int i = blockIdx.x * blockDim.x + threadIdx.x;
    if (i < NEDGE) {
        atomicAdd(&g_cnt_down[ddst[i]], 1);
        atomicAdd(&g_cnt_up[udst[i]], 1);
    }
}

// Per-1024-chunk sums for both arrays in one launch (blocks [0,40)=down).
__global__ void scan_partial_both() {
    __shared__ int red[256];
    int blk = blockIdx.x;
    const int* cnt; int* bsum; int n; int b;
    if (blk < NBLK_DOWN) { cnt = g_cnt_down; bsum = g_bsum_down; n = G_TRUNC; b = blk; }
    else                 { cnt = g_cnt_up;   bsum = g_bsum_up;   n = G_DATA;  b = blk - NBLK_DOWN; }
    int base = b * 1024 + threadIdx.x * 4;
    int s = 0;
#pragma unroll
    for (int j = 0; j < 4; j++) { int i = base + j; if (i < n) s += cnt[i]; }
    red[threadIdx.x] = s;
    __syncthreads();
    for (int off = 128; off > 0; off >>= 1) {
        if (threadIdx.x < off) red[threadIdx.x] += red[threadIdx.x + off];
        __syncthreads();
    }
    if (threadIdx.x == 0) bsum[b] = red[0];
}

// Per-element exclusive scan. Each block redundantly scans the (<=256) block
// sums itself. cnt is left intact (the scatter's countdown cursor consumes it).
__global__ void scan_final_both() {
    int blk = blockIdx.x;
    const int* cnt; int* off; const int* bsum; int n, nblk, b;
    if (blk < NBLK_DOWN) { cnt = g_cnt_down; off = g_off_down; bsum = g_bsum_down;
                           n = G_TRUNC; nblk = NBLK_DOWN; b = blk; }
    else                 { cnt = g_cnt_up;   off = g_off_up;   bsum = g_bsum_up;
                           n = G_DATA;  nblk = NBLK_UP;   b = blk - NBLK_DOWN; }
    int t = threadIdx.x;
    int lane = t & 31, wid = t >> 5;

    __shared__ int s[256];
    int bv = (t < nblk) ? bsum[t] : 0;
    s[t] = bv;
    __syncthreads();
    for (int o = 1; o < 256; o <<= 1) {
        int add = (t >= o) ? s[t - o] : 0;
        __syncthreads();
        s[t] += add;
        __syncthreads();
    }
    int block_off = (b > 0) ? s[b - 1] : 0;
    if (b == 0 && t == 0) off[n] = s[nblk - 1];   // grand total

    int base = b * 1024 + t * 4;
    int v0 = 0, v1 = 0, v2 = 0, v3 = 0;
    if (base + 0 < n) v0 = cnt[base + 0];
    if (base + 1 < n) v1 = cnt[base + 1];
    if (base + 2 < n) v2 = cnt[base + 2];
    if (base + 3 < n) v3 = cnt[base + 3];
    int tsum = v0 + v1 + v2 + v3;
    int x = tsum;
#pragma unroll
    for (int o = 1; o < 32; o <<= 1) {
        int y = __shfl_up_sync(0xffffffffu, x, o);
        if (lane >= o) x += y;
    }
    __shared__ int wsum[8];
    if (lane == 31) wsum[wid] = x;
    __syncthreads();
    if (t == 0) {
        int run = 0;
#pragma unroll
        for (int i = 0; i < 8; i++) { int tmp = wsum[i]; wsum[i] = run; run += tmp; }
    }
    __syncthreads();
    int excl = block_off + wsum[wid] + (x - tsum);
    if (base + 0 < n) off[base + 0] = excl; excl += v0;
    if (base + 1 < n) off[base + 1] = excl; excl += v1;
    if (base + 2 < n) off[base + 2] = excl; excl += v2;
    if (base + 3 < n) off[base + 3] = excl;
}

// Fused scatter + fp32->fp16 convert. The scatter half is L2-atomic bound
// (issue 4.2% in round 6) while the convert half is a pure DRAM stream —
// they overlap on disjoint pipes. Countdown cursor leaves cnt at zero.
// Grid = NEDGE threads exactly; each thread also converts 8 float4s of x.
__global__ void __launch_bounds__(256) scatter_convert_kernel(
    const int* __restrict__ dsrc, const int* __restrict__ ddst,
    const float* __restrict__ dw,
    const int* __restrict__ usrc, const int* __restrict__ udst,
    const float* __restrict__ uw,
    const float* __restrict__ x)
{
    int i = blockIdx.x * blockDim.x + threadIdx.x;

    // ---- scatter (edges -> dst-bucketed arrays) ----
    {
        int d = ddst[i];
        int idx = atomicAdd(&g_cnt_down[d], -1);
        g_edges_down[g_off_down[d] + idx - 1] = make_int2(dsrc[i], __float_as_int(dw[i]));
    }
    {
        int d = udst[i];
        int idx = atomicAdd(&g_cnt_up[d], -1);
        g_edges_up[g_off_up[d] + idx - 1] = make_int2(usrc[i], __float_as_int(uw[i]));
    }

    // ---- convert x slice to fp16 (grid-stride; DRAM stream) ----
    const float4* x4 = reinterpret_cast<const float4*>(x);
    uint2* xh2 = reinterpret_cast<uint2*>(g_xh);
    const int n4 = (G_DATA * FEAT) / 4;               // 8.39M
#pragma unroll
    for (int k = 0; k < 8; k++) {
        int j = i + k * NEDGE;
        if (j < n4) {
            float4 v = __ldcs(&x4[j]);                // streaming read
            __half2 h01 = __floats2half2_rn(v.x, v.y);
            __half2 h23 = __floats2half2_rn(v.z, v.w);
            xh2[j] = make_uint2(*reinterpret_cast<unsigned*>(&h01),
                                *reinterpret_cast<unsigned*>(&h23));
        }
    }
}

// ---------------- gather-only projections ------------------------------------

__device__ __forceinline__ float4 h4_to_f4(uint2 p) {
    float2 a = __half22float2(*reinterpret_cast<__half2*>(&p.x));
    float2 b = __half22float2(*reinterpret_cast<__half2*>(&p.y));
    return make_float4(a.x, a.y, b.x, b.y);
}

// Down: one warp per truncated row. fp16 gather, 4-edge unroll, fp32
// accumulate, fp16 store.
__global__ void __launch_bounds__(256) down_csr_kernel() {
    int g = (blockIdx.x * blockDim.x + threadIdx.x) >> 5;
    int lane = threadIdx.x & 31;
    if (g >= G_TRUNC) return;
    int beg = g_off_down[g];
    int end = g_off_down[g + 1];
    const uint2* xh = reinterpret_cast<const uint2*>(g_xh);
    float4 acc = make_float4(0.f, 0.f, 0.f, 0.f);
    float sw = 0.f;
    int e = beg;
    for (; e + 3 < end; e += 4) {
        int2 r0 = g_edges_down[e];
        int2 r1 = g_edges_down[e + 1];
        int2 r2 = g_edges_down[e + 2];
        int2 r3 = g_edges_down[e + 3];
        float w0 = __int_as_float(r0.y), w1 = __int_as_float(r1.y);
        float w2 = __int_as_float(r2.y), w3 = __int_as_float(r3.y);
        float4 a = h4_to_f4(__ldg(&xh[(size_t)r0.x * (FEAT / 4) + lane]));
        float4 b = h4_to_f4(__ldg(&xh[(size_t)r1.x * (FEAT / 4) + lane]));
        float4 c = h4_to_f4(__ldg(&xh[(size_t)r2.x * (FEAT / 4) + lane]));
        float4 d = h4_to_f4(__ldg(&xh[(size_t)r3.x * (FEAT / 4) + lane]));
        sw += (w0 + w1) + (w2 + w3);
        acc.x = fmaf(w0, a.x, fmaf(w1, b.x, fmaf(w2, c.x, fmaf(w3, d.x, acc.x))));
        acc.y = fmaf(w0, a.y, fmaf(w1, b.y, fmaf(w2, c.y, fmaf(w3, d.y, acc.y))));
        acc.z = fmaf(w0, a.z, fmaf(w1, b.z, fmaf(w2, c.z, fmaf(w3, d.z, acc.z))));
        acc.w = fmaf(w0, a.w, fmaf(w1, b.w, fmaf(w2, c.w, fmaf(w3, d.w, acc.w))));
    }
    for (; e < end; e++) {
        int2 r0 = g_edges_down[e];
        float w0 = __int_as_float(r0.y);
        float4 a = h4_to_f4(__ldg(&xh[(size_t)r0.x * (FEAT / 4) + lane]));
        sw += w0;
        acc.x = fmaf(w0, a.x, acc.x);
        acc.y = fmaf(w0, a.y, acc.y);
        acc.z = fmaf(w0, a.z, acc.z);
        acc.w = fmaf(w0, a.w, acc.w);
    }
    float inv = 1.f / fmaxf(sw, EPSV);
    __half2 h01 = __floats2half2_rn(acc.x * inv, acc.y * inv);
    __half2 h23 = __floats2half2_rn(acc.z * inv, acc.w * inv);
    reinterpret_cast<uint2*>(g_xc + (size_t)g * FEAT)[lane] =
        make_uint2(*reinterpret_cast<unsigned*>(&h01),
                   *reinterpret_cast<unsigned*>(&h23));
}

// Up: one warp per data row. fp16 gather of xc, 4-edge unroll, fp32
// accumulate, streaming fp32 store.
__global__ void __launch_bounds__(256) up_csr_kernel(float* __restrict__ out) {
    int g = (blockIdx.x * blockDim.x + threadIdx.x) >> 5;
    int lane = threadIdx.x & 31;
    if (g >= G_DATA) return;
    int beg = g_off_up[g];
    int end = g_off_up[g + 1];
    const uint2* xc2 = reinterpret_cast<const uint2*>(g_xc);
    float4 acc = make_float4(0.f, 0.f, 0.f, 0.f);
    float sw = 0.f;
    int e = beg;
    for (; e + 3 < end; e += 4) {
        int2 r0 = g_edges_up[e];
        int2 r1 = g_edges_up[e + 1];
        int2 r2 = g_edges_up[e + 2];
        int2 r3 = g_edges_up[e + 3];
        float w0 = __int_as_float(r0.y), w1 = __int_as_float(r1.y);
        float w2 = __int_as_float(r2.y), w3 = __int_as_float(r3.y);
        float4 a = h4_to_f4(__ldg(&xc2[(size_t)r0.x * (FEAT / 4) + lane]));
        float4 b = h4_to_f4(__ldg(&xc2[(size_t)r1.x * (FEAT / 4) + lane]));
        float4 c = h4_to_f4(__ldg(&xc2[(size_t)r2.x * (FEAT / 4) + lane]));
        float4 d = h4_to_f4(__ldg(&xc2[(size_t)r3.x * (FEAT / 4) + lane]));
        sw += (w0 + w1) + (w2 + w3);
        acc.x = fmaf(w0, a.x, fmaf(w1, b.x, fmaf(w2, c.x, fmaf(w3, d.x, acc.x))));
        acc.y = fmaf(w0, a.y, fmaf(w1, b.y, fmaf(w2, c.y, fmaf(w3, d.y, acc.y))));
        acc.z = fmaf(w0, a.z, fmaf(w1, b.z, fmaf(w2, c.z, fmaf(w3, d.z, acc.z))));
        acc.w = fmaf(w0, a.w, fmaf(w1, b.w, fmaf(w2, c.w, fmaf(w3, d.w, acc.w))));
    }
    for (; e < end; e++) {
        int2 r0 = g_edges_up[e];
        float w0 = __int_as_float(r0.y);
        float4 a = h4_to_f4(__ldg(&xc2[(size_t)r0.x * (FEAT / 4) + lane]));
        sw += w0;
        acc.x = fmaf(w0, a.x, acc.x);
        acc.y = fmaf(w0, a.y, acc.y);
        acc.z = fmaf(w0, a.z, acc.z);
        acc.w = fmaf(w0, a.w, acc.w);
    }
    float inv = 1.f / fmaxf(sw, EPSV);
    __stcs(reinterpret_cast<float4*>(out + (size_t)g * FEAT) + lane,
           make_float4(acc.x * inv, acc.y * inv, acc.z * inv, acc.w * inv));
}

// ---------------- launch -----------------------------------------------------

extern "C" void kernel_launch(void* const* d_in, const int* in_sizes, int n_in,
                              void* d_out, int out_size) {
    const float* x        = (const float*)d_in[0];   // (1,2,1,G_DATA,FEAT)
    const int*   down_src = (const int*)  d_in[1];
    const int*   down_dst = (const int*)  d_in[2];
    const float* down_w   = (const float*)d_in[3];
    const int*   up_src   = (const int*)  d_in[4];
    const int*   up_dst   = (const int*)  d_in[5];
    const float* up_w     = (const float*)d_in[6];
    float* out = (float*)d_out;
    (void)in_sizes; (void)n_in; (void)out_size;

    // x[:, -1, ...] slice = second half along dim 1.
    const float* x_slice = x + (size_t)G_DATA * FEAT;

    // CSR build (counters are zero at entry — countdown invariant)
    hist_kernel<<<NEDGE / 256, 256>>>(down_dst, up_dst);
    scan_partial_both<<<NBLK_DOWN + NBLK_UP, 256>>>();
    scan_final_both<<<NBLK_DOWN + NBLK_UP, 256>>>();
    // Fused scatter + convert: L2-atomic work overlaps the DRAM stream.
    scatter_convert_kernel<<<NEDGE / 256, 256>>>(down_src, down_dst, down_w,
                                                 up_src, up_dst, up_w, x_slice);
    // Gather-only projections
    down_csr_kernel<<<(G_TRUNC + 7) / 8, 256>>>();
    up_csr_kernel<<<G_DATA / 8, 256>>>(out);
}